// round 5
// baseline (speedup 1.0000x reference)
#include <cuda_runtime.h>
#include <cuda_fp16.h>

#define NTOK 4096
#define ROWS 16384
#define EPSV 1e-5f
#define SC_L2E 0.18033688011112042f   // 0.125 * log2(e)
#define SKD 72                        // smem half-stride for K/V tiles

// Scratch (allocation-free: __device__ globals)
__device__ __align__(16) __half g_q[ROWS*64];   // pre-scaled by SC_L2E
__device__ __align__(16) __half g_k[ROWS*64];
__device__ __align__(16) __half g_v[ROWS*64];
__device__ float  g_o1[ROWS*64];                // split-0 partial O (unnormalized)
__device__ float  g_o2[ROWS*64];                // split-1 partial O
__device__ float2 g_ml[2*ROWS];                 // per-row (m, l) per split
__device__ float2 g_part[256];
__device__ float2 g_stats[32];

// ---------------- helpers ----------------
__device__ __forceinline__ unsigned f2tf32(float f){
    unsigned u; asm("cvt.rna.tf32.f32 %0,%1;":"=r"(u):"f"(f)); return u;
}
__device__ __forceinline__ unsigned packh2(float lo,float hi){
    unsigned u; asm("cvt.rn.f16x2.f32 %0,%1,%2;":"=r"(u):"f"(hi),"f"(lo)); return u;
}
__device__ __forceinline__ unsigned ex2h2(unsigned a){
    unsigned d; asm("ex2.approx.f16x2 %0,%1;":"=r"(d):"r"(a)); return d;
}
__device__ __forceinline__ void mma_h(float* c,unsigned a0,unsigned a1,unsigned a2,unsigned a3,
                                      unsigned b0,unsigned b1){
    asm volatile("mma.sync.aligned.m16n8k16.row.col.f32.f16.f16.f32 "
        "{%0,%1,%2,%3},{%4,%5,%6,%7},{%8,%9},{%0,%1,%2,%3};"
        :"+f"(c[0]),"+f"(c[1]),"+f"(c[2]),"+f"(c[3])
        :"r"(a0),"r"(a1),"r"(a2),"r"(a3),"r"(b0),"r"(b1));
}
__device__ __forceinline__ void mma_t(float* c,unsigned a0,unsigned a1,unsigned a2,unsigned a3,
                                      unsigned b0,unsigned b1){
    asm volatile("mma.sync.aligned.m16n8k8.row.col.f32.tf32.tf32.f32 "
        "{%0,%1,%2,%3},{%4,%5,%6,%7},{%8,%9},{%0,%1,%2,%3};"
        :"+f"(c[0]),"+f"(c[1]),"+f"(c[2]),"+f"(c[3])
        :"r"(a0),"r"(a1),"r"(a2),"r"(a3),"r"(b0),"r"(b1));
}
__device__ __forceinline__ void ldsm4(unsigned&r0,unsigned&r1,unsigned&r2,unsigned&r3,unsigned a){
    asm volatile("ldmatrix.sync.aligned.m8n8.x4.shared.b16 {%0,%1,%2,%3},[%4];"
        :"=r"(r0),"=r"(r1),"=r"(r2),"=r"(r3):"r"(a));
}
__device__ __forceinline__ void ldsm4t(unsigned&r0,unsigned&r1,unsigned&r2,unsigned&r3,unsigned a){
    asm volatile("ldmatrix.sync.aligned.m8n8.x4.trans.shared.b16 {%0,%1,%2,%3},[%4];"
        :"=r"(r0),"=r"(r1),"=r"(r2),"=r"(r3):"r"(a));
}
__device__ __forceinline__ void cp16(unsigned d,const void* s){
    asm volatile("cp.async.cg.shared.global [%0],[%1],16;"::"r"(d),"l"(s));
}

// ---------------------------------------------------------------------------
// 1a/1b. GroupNorm statistics (split + finalize)
// ---------------------------------------------------------------------------
__global__ void gn_stats_part(const float* __restrict__ x){
    __shared__ float ss[256], sq[256];
    const int t = threadIdx.x;
    const float4* base = (const float4*)x + (size_t)blockIdx.x * 1024;
    float s=0.f,q=0.f;
    #pragma unroll
    for(int i=0;i<4;i++){
        float4 v = base[t + i*256];
        s += (v.x+v.y)+(v.z+v.w);
        q += (v.x*v.x+v.y*v.y)+(v.z*v.z+v.w*v.w);
    }
    ss[t]=s; sq[t]=q; __syncthreads();
    for(int st=128;st;st>>=1){ if(t<st){ss[t]+=ss[t+st]; sq[t]+=sq[t+st];} __syncthreads(); }
    if(!t) g_part[blockIdx.x]=make_float2(ss[0],sq[0]);
}
__global__ void gn_stats_final(){
    const int t=threadIdx.x;
    float s=0.f,q=0.f;
    #pragma unroll
    for(int i=0;i<8;i++){ float2 p=g_part[t*8+i]; s+=p.x; q+=p.y; }
    float mean=s*(1.f/32768.f);
    float var =q*(1.f/32768.f)-mean*mean;
    g_stats[t]=make_float2(mean,rsqrtf(var+EPSV));
}

// ---------------------------------------------------------------------------
// 2. Fused GroupNorm-apply + QKV projection (fp16 mma). 128 rows per block.
//    Q is written pre-scaled by SC_L2E (scores come out in log2 domain).
// ---------------------------------------------------------------------------
__global__ __launch_bounds__(256,1) void qkv_kernel(
        const float* __restrict__ x,
        const float* __restrict__ gamma, const float* __restrict__ beta,
        const float* __restrict__ Wq, const float* __restrict__ bq,
        const float* __restrict__ Wk, const float* __restrict__ bk,
        const float* __restrict__ Wv, const float* __restrict__ bv){
    __shared__ __align__(16) __half sX[128*72];
    __shared__ __align__(16) __half sWt[192*72];
    __shared__ float sB[192];
    const int tid = threadIdx.x;
    const int Rbase = blockIdx.x * 128;

    for(int i=tid;i<4096;i+=256){
        int c=i>>6, n=i&63;
        sWt[n*72+c]        = __float2half(Wq[i]);
        sWt[(64+n)*72+c]   = __float2half(Wk[i]);
        sWt[(128+n)*72+c]  = __float2half(Wv[i]);
    }
    if(tid<64){ sB[tid]=bq[tid]; sB[64+tid]=bk[tid]; sB[128+tid]=bv[tid]; }

    {
        int r = tid>>1, cb=(tid&1)*32;
        int R = Rbase + r;
        int h = (R>>6)&63, bi = R>>12;
        float2 st = g_stats[bi*8+(h>>3)];
        float gc = gamma[h]*st.y, bc = beta[h]-st.x*gc;
        const float4* xr = (const float4*)(x + (size_t)R*64 + cb);
        #pragma unroll
        for(int i=0;i<8;i++){
            float4 v = xr[i];
            ((__half2*)&sX[r*72+cb+i*4])[0] = __floats2half2_rn(fmaf(v.x,gc,bc), fmaf(v.y,gc,bc));
            ((__half2*)&sX[r*72+cb+i*4])[1] = __floats2half2_rn(fmaf(v.z,gc,bc), fmaf(v.w,gc,bc));
        }
    }
    __syncthreads();

    const int warp=tid>>5, lane=tid&31, g=lane>>2, t4=lane&3;
    float acc[24][4];
    #pragma unroll
    for(int n=0;n<24;n++) acc[n][0]=acc[n][1]=acc[n][2]=acc[n][3]=0.f;

    #pragma unroll
    for(int kk=0;kk<4;kk++){
        int r0=warp*16+g;
        unsigned a0=*(const unsigned*)&sX[ r0   *72 + kk*16 + 2*t4];
        unsigned a1=*(const unsigned*)&sX[(r0+8)*72 + kk*16 + 2*t4];
        unsigned a2=*(const unsigned*)&sX[ r0   *72 + kk*16 + 2*t4 + 8];
        unsigned a3=*(const unsigned*)&sX[(r0+8)*72 + kk*16 + 2*t4 + 8];
        #pragma unroll
        for(int nt=0;nt<24;nt++){
            unsigned b0=*(const unsigned*)&sWt[(nt*8+g)*72 + kk*16 + 2*t4];
            unsigned b1=*(const unsigned*)&sWt[(nt*8+g)*72 + kk*16 + 2*t4 + 8];
            mma_h(acc[nt],a0,a1,a2,a3,b0,b1);
        }
    }

    int R0 = Rbase + warp*16 + g;
    #pragma unroll
    for(int nt=0;nt<24;nt++){
        int n = nt*8 + 2*t4;
        int col = (nt&7)*8 + 2*t4;
        float b0f=sB[n], b1f=sB[n+1];
        float v0=acc[nt][0]+b0f, v1=acc[nt][1]+b1f;
        float v2=acc[nt][2]+b0f, v3=acc[nt][3]+b1f;
        if(nt<8){ v0*=SC_L2E; v1*=SC_L2E; v2*=SC_L2E; v3*=SC_L2E; }
        __half* dst = (nt<8)? g_q : (nt<16)? g_k : g_v;
        *(unsigned*)&dst[(size_t)R0*64+col]     = packh2(v0, v1);
        *(unsigned*)&dst[(size_t)(R0+8)*64+col] = packh2(v2, v3);
    }
}

// ---------------------------------------------------------------------------
// 3. Flash attention, fp16 mma. 64-query blocks (4 warps), split-KV x2.
//    Register-resident softmax; l computed by a ones-column HMMA; exp via
//    ex2.approx.f16x2. Writes unnormalized partial O + (m,l).
// ---------------------------------------------------------------------------
__global__ __launch_bounds__(128,3) void attn_kernel(){
    __shared__ __align__(16) __half sK[2][64*SKD];
    __shared__ __align__(16) __half sV[2][64*SKD];

    const int tid=threadIdx.x, warp=tid>>5, lane=tid&31;
    const int g=lane>>2, t4=lane&3, q8=lane>>3, rr=lane&7;
    const int split = blockIdx.x >> 8;
    const int bq    = blockIdx.x & 255;
    const int b     = bq >> 6;
    const int qbase = (bq & 63) * 64;
    const __half* Qg = g_q + ((size_t)b*NTOK+qbase)*64;
    const __half* Kg = g_k + (size_t)b*NTOK*64;
    const __half* Vg = g_v + (size_t)b*NTOK*64;
    const int r0 = warp*16+g;
    const unsigned ones2 = 0x3C003C00u;  // half2(1,1)

    unsigned skb[2], svb[2];
    skb[0]=(unsigned)__cvta_generic_to_shared(&sK[0][0]);
    skb[1]=(unsigned)__cvta_generic_to_shared(&sK[1][0]);
    svb[0]=(unsigned)__cvta_generic_to_shared(&sV[0][0]);
    svb[1]=(unsigned)__cvta_generic_to_shared(&sV[1][0]);

    unsigned qa[4][4];
    #pragma unroll
    for(int kk=0;kk<4;kk++){
        qa[kk][0]=*(const unsigned*)&Qg[(size_t) r0   *64 + kk*16 + 2*t4];
        qa[kk][1]=*(const unsigned*)&Qg[(size_t)(r0+8)*64 + kk*16 + 2*t4];
        qa[kk][2]=*(const unsigned*)&Qg[(size_t) r0   *64 + kk*16 + 2*t4 + 8];
        qa[kk][3]=*(const unsigned*)&Qg[(size_t)(r0+8)*64 + kk*16 + 2*t4 + 8];
    }
    float o[8][4];
    #pragma unroll
    for(int n=0;n<8;n++) o[n][0]=o[n][1]=o[n][2]=o[n][3]=0.f;
    float lacc[4] = {0.f,0.f,0.f,0.f};
    float m0=-1e30f, m1=-1e30f;

    const int t0 = split * 32;   // 32 tiles of 64 keys per split
    auto issue = [&](int kt,int buf){
        const __half* ks = Kg + (size_t)kt*64*64;
        const __half* vs = Vg + (size_t)kt*64*64;
        #pragma unroll
        for(int i=0;i<4;i++){
            int idx = tid + i*128;
            int row = idx>>3, c=(idx&7)*8;
            cp16(skb[buf] + (row*SKD+c)*2, ks + row*64 + c);
            cp16(svb[buf] + (row*SKD+c)*2, vs + row*64 + c);
        }
    };
    issue(t0,0);
    asm volatile("cp.async.commit_group;");

    for(int it=0; it<32; it++){
        const int cur=it&1;
        if(it<31){
            issue(t0+it+1,cur^1);
            asm volatile("cp.async.commit_group;");
            asm volatile("cp.async.wait_group 1;");
        } else {
            asm volatile("cp.async.wait_group 0;");
        }
        __syncthreads();

        // ---- S = Q @ K^T (already in log2 domain) ----
        float s[8][4];
        #pragma unroll
        for(int n=0;n<8;n++) s[n][0]=s[n][1]=s[n][2]=s[n][3]=0.f;
        #pragma unroll
        for(int kk=0;kk<4;kk++){
            #pragma unroll
            for(int np=0;np<4;np++){
                unsigned b00,b01,b10,b11;
                unsigned a = skb[cur] + (((np*16 + (q8>>1)*8 + rr)*SKD) + kk*16 + (q8&1)*8)*2;
                ldsm4(b00,b01,b10,b11,a);
                mma_h(s[2*np  ], qa[kk][0],qa[kk][1],qa[kk][2],qa[kk][3], b00,b01);
                mma_h(s[2*np+1], qa[kk][0],qa[kk][1],qa[kk][2],qa[kk][3], b10,b11);
            }
        }

        // ---- online softmax ----
        float mx0=-1e30f, mx1=-1e30f;
        #pragma unroll
        for(int n=0;n<8;n++){
            mx0=fmaxf(mx0,fmaxf(s[n][0],s[n][1]));
            mx1=fmaxf(mx1,fmaxf(s[n][2],s[n][3]));
        }
        mx0=fmaxf(mx0,__shfl_xor_sync(0xffffffffu,mx0,1));
        mx0=fmaxf(mx0,__shfl_xor_sync(0xffffffffu,mx0,2));
        mx1=fmaxf(mx1,__shfl_xor_sync(0xffffffffu,mx1,1));
        mx1=fmaxf(mx1,__shfl_xor_sync(0xffffffffu,mx1,2));
        float mn0=fmaxf(m0,mx0), mn1=fmaxf(m1,mx1);
        float c0=exp2f(m0-mn0), c1=exp2f(m1-mn1);
        m0=mn0; m1=mn1;
        unsigned pa0[8], pa1[8];
        #pragma unroll
        for(int n=0;n<8;n++){
            pa0[n]=ex2h2(packh2(s[n][0]-mn0, s[n][1]-mn0));
            pa1[n]=ex2h2(packh2(s[n][2]-mn1, s[n][3]-mn1));
        }
        #pragma unroll
        for(int n=0;n<8;n++){ o[n][0]*=c0; o[n][1]*=c0; o[n][2]*=c1; o[n][3]*=c1; }
        lacc[0]*=c0; lacc[1]*=c0; lacc[2]*=c1; lacc[3]*=c1;

        // ---- O += P @ V  and  l += P @ 1 ----
        #pragma unroll
        for(int kk=0;kk<4;kk++){
            unsigned a0=pa0[2*kk], a1=pa1[2*kk], a2=pa0[2*kk+1], a3=pa1[2*kk+1];
            mma_h(lacc, a0,a1,a2,a3, ones2,ones2);
            #pragma unroll
            for(int np=0;np<4;np++){
                unsigned b00,b01,b10,b11;
                unsigned a = svb[cur] + (((kk*16 + (q8&1)*8 + rr)*SKD) + np*16 + (q8>>1)*8)*2;
                ldsm4t(b00,b01,b10,b11,a);
                mma_h(o[2*np  ], a0,a1,a2,a3, b00,b01);
                mma_h(o[2*np+1], a0,a1,a2,a3, b10,b11);
            }
        }
        __syncthreads();
    }

    float* Og = (split ? g_o2 : g_o1) + ((size_t)b*NTOK+qbase)*64;
    #pragma unroll
    for(int n=0;n<8;n++){
        *(float2*)&Og[(size_t) r0   *64 + n*8 + 2*t4] = make_float2(o[n][0], o[n][1]);
        *(float2*)&Og[(size_t)(r0+8)*64 + n*8 + 2*t4] = make_float2(o[n][2], o[n][3]);
    }
    if(t4==0){
        int Rg = b*NTOK + qbase;
        g_ml[(size_t)split*ROWS + Rg + r0    ] = make_float2(m0, lacc[0]);
        g_ml[(size_t)split*ROWS + Rg + r0 + 8] = make_float2(m1, lacc[2]);
    }
}

// ---------------------------------------------------------------------------
// 4. Split combine + output projection (tf32 mma) + GN residual.
// ---------------------------------------------------------------------------
__global__ __launch_bounds__(256,1) void final_kernel(
        const float* __restrict__ x,
        const float* __restrict__ gamma, const float* __restrict__ beta,
        const float* __restrict__ Wo, const float* __restrict__ bo,
        float* __restrict__ out){
    extern __shared__ float sm[];
    float* sA  = sm;                // 128*68
    float* sWt = sm + 128*68;       // 64*68
    float* sB  = sWt + 64*68;       // 64
    const int tid=threadIdx.x;
    const int Rbase = blockIdx.x*128;

    for(int i=tid;i<4096;i+=256){
        int c=i>>6, n=i&63;
        sWt[n*68+c] = __uint_as_float(f2tf32(Wo[i]));
    }
    if(tid<64) sB[tid]=bo[tid];
    {
        int r=tid>>1, cb=(tid&1)*32;
        int R = Rbase + r;
        float2 mla = g_ml[R], mlb = g_ml[ROWS + R];
        float M = fmaxf(mla.x, mlb.x);
        float wa = exp2f(mla.x - M), wb = exp2f(mlb.x - M);
        float L  = wa*mla.y + wb*mlb.y;
        float fa = wa / L, fb = wb / L;
        const float4* oa=(const float4*)(g_o1+(size_t)R*64+cb);
        const float4* ob=(const float4*)(g_o2+(size_t)R*64+cb);
        #pragma unroll
        for(int i=0;i<8;i++){
            float4 va=oa[i], vb=ob[i];
            sA[r*68+cb+i*4+0]=__uint_as_float(f2tf32(va.x*fa + vb.x*fb));
            sA[r*68+cb+i*4+1]=__uint_as_float(f2tf32(va.y*fa + vb.y*fb));
            sA[r*68+cb+i*4+2]=__uint_as_float(f2tf32(va.z*fa + vb.z*fb));
            sA[r*68+cb+i*4+3]=__uint_as_float(f2tf32(va.w*fa + vb.w*fb));
        }
    }
    __syncthreads();

    const int warp=tid>>5, lane=tid&31, g=lane>>2, t4=lane&3;
    float acc[8][4];
    #pragma unroll
    for(int n=0;n<8;n++) acc[n][0]=acc[n][1]=acc[n][2]=acc[n][3]=0.f;

    #pragma unroll
    for(int kk=0;kk<8;kk++){
        int r0=warp*16+g;
        unsigned a0=__float_as_uint(sA[ r0   *68 + kk*8 + t4]);
        unsigned a1=__float_as_uint(sA[(r0+8)*68 + kk*8 + t4]);
        unsigned a2=__float_as_uint(sA[ r0   *68 + kk*8 + t4 + 4]);
        unsigned a3=__float_as_uint(sA[(r0+8)*68 + kk*8 + t4 + 4]);
        #pragma unroll
        for(int nt=0;nt<8;nt++){
            unsigned b0=__float_as_uint(sWt[(nt*8+g)*68 + kk*8 + t4]);
            unsigned b1=__float_as_uint(sWt[(nt*8+g)*68 + kk*8 + t4 + 4]);
            mma_t(acc[nt],a0,a1,a2,a3,b0,b1);
        }
    }

    int R0 = Rbase + warp*16 + g;
    int h=(R0>>6)&63, bi=R0>>12;
    float2 st=g_stats[bi*8+(h>>3)];
    float gc=gamma[h]*st.y, bc=beta[h]-st.x*gc;
    #pragma unroll
    for(int nt=0;nt<8;nt++){
        int col=nt*8+2*t4;
        float2 x0=*(const float2*)&x[(size_t)R0*64+col];
        float2 x1=*(const float2*)&x[(size_t)(R0+8)*64+col];
        float2 r0v, r1v;
        r0v.x=fmaf(x0.x,gc,bc)+acc[nt][0]+sB[col];
        r0v.y=fmaf(x0.y,gc,bc)+acc[nt][1]+sB[col+1];
        r1v.x=fmaf(x1.x,gc,bc)+acc[nt][2]+sB[col];
        r1v.y=fmaf(x1.y,gc,bc)+acc[nt][3]+sB[col+1];
        *(float2*)&out[(size_t)R0*64+col]=r0v;
        *(float2*)&out[(size_t)(R0+8)*64+col]=r1v;
    }
}

// ---------------------------------------------------------------------------
extern "C" void kernel_launch(void* const* d_in, const int* in_sizes, int n_in,
                              void* d_out, int out_size) {
    const float* x     = (const float*)d_in[0];
    const float* gamma = (const float*)d_in[1];
    const float* beta  = (const float*)d_in[2];
    const float* Wq    = (const float*)d_in[3];
    const float* bq    = (const float*)d_in[4];
    const float* Wk    = (const float*)d_in[5];
    const float* bk    = (const float*)d_in[6];
    const float* Wv    = (const float*)d_in[7];
    const float* bv    = (const float*)d_in[8];
    const float* Wo    = (const float*)d_in[9];
    const float* bo    = (const float*)d_in[10];
    float* out = (float*)d_out;

    const int final_smem = (128*68 + 64*68 + 64)*4;   // 52480 B
    cudaFuncSetAttribute(final_kernel, cudaFuncAttributeMaxDynamicSharedMemorySize, final_smem);

    gn_stats_part<<<256,256>>>(x);
    gn_stats_final<<<1,32>>>();
    qkv_kernel<<<128,256>>>(x, gamma, beta, Wq, bq, Wk, bk, Wv, bv);
    attn_kernel<<<512,128>>>();
    final_kernel<<<128,256,final_smem>>>(x, gamma, beta, Wo, bo, out);
}

// round 6
// speedup vs baseline: 1.6012x; 1.6012x over previous
#include <cuda_runtime.h>
#include <cuda_fp16.h>

#define NTOK 4096
#define ROWS 16384
#define EPSV 1e-5f
#define SC_L2E 0.18033688011112042f   // 0.125 * log2(e)
#define SKD 72                        // smem half-stride for K/V tiles

// Scratch (allocation-free: __device__ globals)
__device__ __align__(16) __half g_q[ROWS*64];   // pre-scaled by SC_L2E
__device__ __align__(16) __half g_k[ROWS*64];
__device__ __align__(16) __half g_v[ROWS*64];
__device__ float  g_o1[ROWS*64];                // split-0 partial O (unnormalized)
__device__ float  g_o2[ROWS*64];                // split-1 partial O
__device__ float2 g_ml[2*ROWS];                 // per-row (m, l) per split
__device__ float2 g_part[256];
__device__ float2 g_stats[32];

// ---------------- helpers ----------------
__device__ __forceinline__ unsigned f2tf32(float f){
    unsigned u; asm("cvt.rna.tf32.f32 %0,%1;":"=r"(u):"f"(f)); return u;
}
__device__ __forceinline__ unsigned packh2(float lo,float hi){
    unsigned u; asm("cvt.rn.f16x2.f32 %0,%1,%2;":"=r"(u):"f"(hi),"f"(lo)); return u;
}
__device__ __forceinline__ unsigned ex2h2(unsigned a){
    unsigned d; asm("ex2.approx.f16x2 %0,%1;":"=r"(d):"r"(a)); return d;
}
__device__ __forceinline__ void mma_h(float* c,unsigned a0,unsigned a1,unsigned a2,unsigned a3,
                                      unsigned b0,unsigned b1){
    asm volatile("mma.sync.aligned.m16n8k16.row.col.f32.f16.f16.f32 "
        "{%0,%1,%2,%3},{%4,%5,%6,%7},{%8,%9},{%0,%1,%2,%3};"
        :"+f"(c[0]),"+f"(c[1]),"+f"(c[2]),"+f"(c[3])
        :"r"(a0),"r"(a1),"r"(a2),"r"(a3),"r"(b0),"r"(b1));
}
__device__ __forceinline__ void mma_t(float* c,unsigned a0,unsigned a1,unsigned a2,unsigned a3,
                                      unsigned b0,unsigned b1){
    asm volatile("mma.sync.aligned.m16n8k8.row.col.f32.tf32.tf32.f32 "
        "{%0,%1,%2,%3},{%4,%5,%6,%7},{%8,%9},{%0,%1,%2,%3};"
        :"+f"(c[0]),"+f"(c[1]),"+f"(c[2]),"+f"(c[3])
        :"r"(a0),"r"(a1),"r"(a2),"r"(a3),"r"(b0),"r"(b1));
}
__device__ __forceinline__ void ldsm4(unsigned&r0,unsigned&r1,unsigned&r2,unsigned&r3,unsigned a){
    asm volatile("ldmatrix.sync.aligned.m8n8.x4.shared.b16 {%0,%1,%2,%3},[%4];"
        :"=r"(r0),"=r"(r1),"=r"(r2),"=r"(r3):"r"(a));
}
__device__ __forceinline__ void ldsm4t(unsigned&r0,unsigned&r1,unsigned&r2,unsigned&r3,unsigned a){
    asm volatile("ldmatrix.sync.aligned.m8n8.x4.trans.shared.b16 {%0,%1,%2,%3},[%4];"
        :"=r"(r0),"=r"(r1),"=r"(r2),"=r"(r3):"r"(a));
}
__device__ __forceinline__ void cp16(unsigned d,const void* s){
    asm volatile("cp.async.cg.shared.global [%0],[%1],16;"::"r"(d),"l"(s));
}

// ---------------------------------------------------------------------------
// 1a/1b. GroupNorm statistics (split + finalize)
// ---------------------------------------------------------------------------
__global__ void gn_stats_part(const float* __restrict__ x){
    __shared__ float ss[256], sq[256];
    const int t = threadIdx.x;
    const float4* base = (const float4*)x + (size_t)blockIdx.x * 1024;
    float s=0.f,q=0.f;
    #pragma unroll
    for(int i=0;i<4;i++){
        float4 v = base[t + i*256];
        s += (v.x+v.y)+(v.z+v.w);
        q += (v.x*v.x+v.y*v.y)+(v.z*v.z+v.w*v.w);
    }
    ss[t]=s; sq[t]=q; __syncthreads();
    for(int st=128;st;st>>=1){ if(t<st){ss[t]+=ss[t+st]; sq[t]+=sq[t+st];} __syncthreads(); }
    if(!t) g_part[blockIdx.x]=make_float2(ss[0],sq[0]);
}
__global__ void gn_stats_final(){
    const int t=threadIdx.x;
    float s=0.f,q=0.f;
    #pragma unroll
    for(int i=0;i<8;i++){ float2 p=g_part[t*8+i]; s+=p.x; q+=p.y; }
    float mean=s*(1.f/32768.f);
    float var =q*(1.f/32768.f)-mean*mean;
    g_stats[t]=make_float2(mean,rsqrtf(var+EPSV));
}

// ---------------------------------------------------------------------------
// 2. Fused GroupNorm-apply + QKV projection (fp16 mma). 128 rows per block.
//    Q is written pre-scaled by SC_L2E (scores come out in log2 domain).
// ---------------------------------------------------------------------------
__global__ __launch_bounds__(256,1) void qkv_kernel(
        const float* __restrict__ x,
        const float* __restrict__ gamma, const float* __restrict__ beta,
        const float* __restrict__ Wq, const float* __restrict__ bq,
        const float* __restrict__ Wk, const float* __restrict__ bk,
        const float* __restrict__ Wv, const float* __restrict__ bv){
    __shared__ __align__(16) __half sX[128*72];
    __shared__ __align__(16) __half sWt[192*72];
    __shared__ float sB[192];
    const int tid = threadIdx.x;
    const int Rbase = blockIdx.x * 128;

    for(int i=tid;i<4096;i+=256){
        int c=i>>6, n=i&63;
        sWt[n*72+c]        = __float2half(Wq[i]);
        sWt[(64+n)*72+c]   = __float2half(Wk[i]);
        sWt[(128+n)*72+c]  = __float2half(Wv[i]);
    }
    if(tid<64){ sB[tid]=bq[tid]; sB[64+tid]=bk[tid]; sB[128+tid]=bv[tid]; }

    {
        int r = tid>>1, cb=(tid&1)*32;
        int R = Rbase + r;
        int h = (R>>6)&63, bi = R>>12;
        float2 st = g_stats[bi*8+(h>>3)];
        float gc = gamma[h]*st.y, bc = beta[h]-st.x*gc;
        const float4* xr = (const float4*)(x + (size_t)R*64 + cb);
        #pragma unroll
        for(int i=0;i<8;i++){
            float4 v = xr[i];
            ((__half2*)&sX[r*72+cb+i*4])[0] = __floats2half2_rn(fmaf(v.x,gc,bc), fmaf(v.y,gc,bc));
            ((__half2*)&sX[r*72+cb+i*4])[1] = __floats2half2_rn(fmaf(v.z,gc,bc), fmaf(v.w,gc,bc));
        }
    }
    __syncthreads();

    const int warp=tid>>5, lane=tid&31, g=lane>>2, t4=lane&3;
    float acc[24][4];
    #pragma unroll
    for(int n=0;n<24;n++) acc[n][0]=acc[n][1]=acc[n][2]=acc[n][3]=0.f;

    #pragma unroll
    for(int kk=0;kk<4;kk++){
        int r0=warp*16+g;
        unsigned a0=*(const unsigned*)&sX[ r0   *72 + kk*16 + 2*t4];
        unsigned a1=*(const unsigned*)&sX[(r0+8)*72 + kk*16 + 2*t4];
        unsigned a2=*(const unsigned*)&sX[ r0   *72 + kk*16 + 2*t4 + 8];
        unsigned a3=*(const unsigned*)&sX[(r0+8)*72 + kk*16 + 2*t4 + 8];
        #pragma unroll
        for(int nt=0;nt<24;nt++){
            unsigned b0=*(const unsigned*)&sWt[(nt*8+g)*72 + kk*16 + 2*t4];
            unsigned b1=*(const unsigned*)&sWt[(nt*8+g)*72 + kk*16 + 2*t4 + 8];
            mma_h(acc[nt],a0,a1,a2,a3,b0,b1);
        }
    }

    int R0 = Rbase + warp*16 + g;
    #pragma unroll
    for(int nt=0;nt<24;nt++){
        int n = nt*8 + 2*t4;
        int col = (nt&7)*8 + 2*t4;
        float b0f=sB[n], b1f=sB[n+1];
        float v0=acc[nt][0]+b0f, v1=acc[nt][1]+b1f;
        float v2=acc[nt][2]+b0f, v3=acc[nt][3]+b1f;
        if(nt<8){ v0*=SC_L2E; v1*=SC_L2E; v2*=SC_L2E; v3*=SC_L2E; }
        __half* dst = (nt<8)? g_q : (nt<16)? g_k : g_v;
        *(unsigned*)&dst[(size_t)R0*64+col]     = packh2(v0, v1);
        *(unsigned*)&dst[(size_t)(R0+8)*64+col] = packh2(v2, v3);
    }
}

// ---------------------------------------------------------------------------
// 3. Flash attention, fp16 mma. 128-query blocks (8 warps), split-KV x2,
//    2 CTAs/SM. Register-resident softmax; l via ones-column HMMA; exp via
//    ex2.approx.f16x2. Writes unnormalized partial O + (m,l).
// ---------------------------------------------------------------------------
__global__ __launch_bounds__(256,2) void attn_kernel(){
    __shared__ __align__(16) __half sK[2][64*SKD];
    __shared__ __align__(16) __half sV[2][64*SKD];

    const int tid=threadIdx.x, warp=tid>>5, lane=tid&31;
    const int g=lane>>2, t4=lane&3, q8=lane>>3, rr=lane&7;
    const int split = blockIdx.x >> 7;           // 0..1
    const int bq    = blockIdx.x & 127;          // b*32 + qblock
    const int b     = bq >> 5;
    const int qbase = (bq & 31) * 128;
    const __half* Qg = g_q + ((size_t)b*NTOK+qbase)*64;
    const __half* Kg = g_k + (size_t)b*NTOK*64;
    const __half* Vg = g_v + (size_t)b*NTOK*64;
    const int r0 = warp*16+g;
    const unsigned ones2 = 0x3C003C00u;  // half2(1,1)

    unsigned skb[2], svb[2];
    skb[0]=(unsigned)__cvta_generic_to_shared(&sK[0][0]);
    skb[1]=(unsigned)__cvta_generic_to_shared(&sK[1][0]);
    svb[0]=(unsigned)__cvta_generic_to_shared(&sV[0][0]);
    svb[1]=(unsigned)__cvta_generic_to_shared(&sV[1][0]);

    unsigned qa[4][4];
    #pragma unroll
    for(int kk=0;kk<4;kk++){
        qa[kk][0]=*(const unsigned*)&Qg[(size_t) r0   *64 + kk*16 + 2*t4];
        qa[kk][1]=*(const unsigned*)&Qg[(size_t)(r0+8)*64 + kk*16 + 2*t4];
        qa[kk][2]=*(const unsigned*)&Qg[(size_t) r0   *64 + kk*16 + 2*t4 + 8];
        qa[kk][3]=*(const unsigned*)&Qg[(size_t)(r0+8)*64 + kk*16 + 2*t4 + 8];
    }
    float o[8][4];
    #pragma unroll
    for(int n=0;n<8;n++) o[n][0]=o[n][1]=o[n][2]=o[n][3]=0.f;
    float lacc[4] = {0.f,0.f,0.f,0.f};
    float m0=-1e30f, m1=-1e30f;

    const int t0 = split * 32;   // 32 tiles of 64 keys per split
    auto issue = [&](int kt,int buf){
        const __half* ks = Kg + (size_t)kt*64*64;
        const __half* vs = Vg + (size_t)kt*64*64;
        #pragma unroll
        for(int i=0;i<2;i++){
            int idx = tid + i*256;
            int row = idx>>3, c=(idx&7)*8;
            cp16(skb[buf] + (row*SKD+c)*2, ks + row*64 + c);
            cp16(svb[buf] + (row*SKD+c)*2, vs + row*64 + c);
        }
    };
    issue(t0,0);
    asm volatile("cp.async.commit_group;");

    for(int it=0; it<32; it++){
        const int cur=it&1;
        if(it<31){
            issue(t0+it+1,cur^1);
            asm volatile("cp.async.commit_group;");
            asm volatile("cp.async.wait_group 1;");
        } else {
            asm volatile("cp.async.wait_group 0;");
        }
        __syncthreads();

        // ---- S = Q @ K^T (already in log2 domain) ----
        float s[8][4];
        #pragma unroll
        for(int n=0;n<8;n++) s[n][0]=s[n][1]=s[n][2]=s[n][3]=0.f;
        #pragma unroll
        for(int kk=0;kk<4;kk++){
            #pragma unroll
            for(int np=0;np<4;np++){
                unsigned b00,b01,b10,b11;
                unsigned a = skb[cur] + (((np*16 + (q8>>1)*8 + rr)*SKD) + kk*16 + (q8&1)*8)*2;
                ldsm4(b00,b01,b10,b11,a);
                mma_h(s[2*np  ], qa[kk][0],qa[kk][1],qa[kk][2],qa[kk][3], b00,b01);
                mma_h(s[2*np+1], qa[kk][0],qa[kk][1],qa[kk][2],qa[kk][3], b10,b11);
            }
        }

        // ---- online softmax ----
        float mx0=-1e30f, mx1=-1e30f;
        #pragma unroll
        for(int n=0;n<8;n++){
            mx0=fmaxf(mx0,fmaxf(s[n][0],s[n][1]));
            mx1=fmaxf(mx1,fmaxf(s[n][2],s[n][3]));
        }
        mx0=fmaxf(mx0,__shfl_xor_sync(0xffffffffu,mx0,1));
        mx0=fmaxf(mx0,__shfl_xor_sync(0xffffffffu,mx0,2));
        mx1=fmaxf(mx1,__shfl_xor_sync(0xffffffffu,mx1,1));
        mx1=fmaxf(mx1,__shfl_xor_sync(0xffffffffu,mx1,2));
        float mn0=fmaxf(m0,mx0), mn1=fmaxf(m1,mx1);
        float c0=exp2f(m0-mn0), c1=exp2f(m1-mn1);
        m0=mn0; m1=mn1;
        unsigned pa0[8], pa1[8];
        #pragma unroll
        for(int n=0;n<8;n++){
            pa0[n]=ex2h2(packh2(s[n][0]-mn0, s[n][1]-mn0));
            pa1[n]=ex2h2(packh2(s[n][2]-mn1, s[n][3]-mn1));
        }
        #pragma unroll
        for(int n=0;n<8;n++){ o[n][0]*=c0; o[n][1]*=c0; o[n][2]*=c1; o[n][3]*=c1; }
        lacc[0]*=c0; lacc[1]*=c0; lacc[2]*=c1; lacc[3]*=c1;

        // ---- O += P @ V  and  l += P @ 1 ----
        #pragma unroll
        for(int kk=0;kk<4;kk++){
            unsigned a0=pa0[2*kk], a1=pa1[2*kk], a2=pa0[2*kk+1], a3=pa1[2*kk+1];
            mma_h(lacc, a0,a1,a2,a3, ones2,ones2);
            #pragma unroll
            for(int np=0;np<4;np++){
                unsigned b00,b01,b10,b11;
                unsigned a = svb[cur] + (((kk*16 + (q8&1)*8 + rr)*SKD) + np*16 + (q8>>1)*8)*2;
                ldsm4t(b00,b01,b10,b11,a);
                mma_h(o[2*np  ], a0,a1,a2,a3, b00,b01);
                mma_h(o[2*np+1], a0,a1,a2,a3, b10,b11);
            }
        }
        __syncthreads();
    }

    float* Og = (split ? g_o2 : g_o1) + ((size_t)b*NTOK+qbase)*64;
    #pragma unroll
    for(int n=0;n<8;n++){
        *(float2*)&Og[(size_t) r0   *64 + n*8 + 2*t4] = make_float2(o[n][0], o[n][1]);
        *(float2*)&Og[(size_t)(r0+8)*64 + n*8 + 2*t4] = make_float2(o[n][2], o[n][3]);
    }
    if(t4==0){
        int Rg = b*NTOK + qbase;
        g_ml[(size_t)split*ROWS + Rg + r0    ] = make_float2(m0, lacc[0]);
        g_ml[(size_t)split*ROWS + Rg + r0 + 8] = make_float2(m1, lacc[2]);
    }
}

// ---------------------------------------------------------------------------
// 4. Split combine + output projection (tf32 mma) + GN residual.
// ---------------------------------------------------------------------------
__global__ __launch_bounds__(256,1) void final_kernel(
        const float* __restrict__ x,
        const float* __restrict__ gamma, const float* __restrict__ beta,
        const float* __restrict__ Wo, const float* __restrict__ bo,
        float* __restrict__ out){
    extern __shared__ float sm[];
    float* sA  = sm;                // 128*68
    float* sWt = sm + 128*68;       // 64*68
    float* sB  = sWt + 64*68;       // 64
    const int tid=threadIdx.x;
    const int Rbase = blockIdx.x*128;

    for(int i=tid;i<4096;i+=256){
        int c=i>>6, n=i&63;
        sWt[n*68+c] = __uint_as_float(f2tf32(Wo[i]));
    }
    if(tid<64) sB[tid]=bo[tid];
    {
        int r=tid>>1, cb=(tid&1)*32;
        int R = Rbase + r;
        float2 mla = g_ml[R], mlb = g_ml[ROWS + R];
        float M = fmaxf(mla.x, mlb.x);
        float wa = exp2f(mla.x - M), wb = exp2f(mlb.x - M);
        float L  = wa*mla.y + wb*mlb.y;
        float fa = wa / L, fb = wb / L;
        const float4* oa=(const float4*)(g_o1+(size_t)R*64+cb);
        const float4* ob=(const float4*)(g_o2+(size_t)R*64+cb);
        #pragma unroll
        for(int i=0;i<8;i++){
            float4 va=oa[i], vb=ob[i];
            sA[r*68+cb+i*4+0]=__uint_as_float(f2tf32(va.x*fa + vb.x*fb));
            sA[r*68+cb+i*4+1]=__uint_as_float(f2tf32(va.y*fa + vb.y*fb));
            sA[r*68+cb+i*4+2]=__uint_as_float(f2tf32(va.z*fa + vb.z*fb));
            sA[r*68+cb+i*4+3]=__uint_as_float(f2tf32(va.w*fa + vb.w*fb));
        }
    }
    __syncthreads();

    const int warp=tid>>5, lane=tid&31, g=lane>>2, t4=lane&3;
    float acc[8][4];
    #pragma unroll
    for(int n=0;n<8;n++) acc[n][0]=acc[n][1]=acc[n][2]=acc[n][3]=0.f;

    #pragma unroll
    for(int kk=0;kk<8;kk++){
        int r0=warp*16+g;
        unsigned a0=__float_as_uint(sA[ r0   *68 + kk*8 + t4]);
        unsigned a1=__float_as_uint(sA[(r0+8)*68 + kk*8 + t4]);
        unsigned a2=__float_as_uint(sA[ r0   *68 + kk*8 + t4 + 4]);
        unsigned a3=__float_as_uint(sA[(r0+8)*68 + kk*8 + t4 + 4]);
        #pragma unroll
        for(int nt=0;nt<8;nt++){
            unsigned b0=__float_as_uint(sWt[(nt*8+g)*68 + kk*8 + t4]);
            unsigned b1=__float_as_uint(sWt[(nt*8+g)*68 + kk*8 + t4 + 4]);
            mma_t(acc[nt],a0,a1,a2,a3,b0,b1);
        }
    }

    int R0 = Rbase + warp*16 + g;
    int h=(R0>>6)&63, bi=R0>>12;
    float2 st=g_stats[bi*8+(h>>3)];
    float gc=gamma[h]*st.y, bc=beta[h]-st.x*gc;
    #pragma unroll
    for(int nt=0;nt<8;nt++){
        int col=nt*8+2*t4;
        float2 x0=*(const float2*)&x[(size_t)R0*64+col];
        float2 x1=*(const float2*)&x[(size_t)(R0+8)*64+col];
        float2 r0v, r1v;
        r0v.x=fmaf(x0.x,gc,bc)+acc[nt][0]+sB[col];
        r0v.y=fmaf(x0.y,gc,bc)+acc[nt][1]+sB[col+1];
        r1v.x=fmaf(x1.x,gc,bc)+acc[nt][2]+sB[col];
        r1v.y=fmaf(x1.y,gc,bc)+acc[nt][3]+sB[col+1];
        *(float2*)&out[(size_t)R0*64+col]=r0v;
        *(float2*)&out[(size_t)(R0+8)*64+col]=r1v;
    }
}

// ---------------------------------------------------------------------------
extern "C" void kernel_launch(void* const* d_in, const int* in_sizes, int n_in,
                              void* d_out, int out_size) {
    const float* x     = (const float*)d_in[0];
    const float* gamma = (const float*)d_in[1];
    const float* beta  = (const float*)d_in[2];
    const float* Wq    = (const float*)d_in[3];
    const float* bq    = (const float*)d_in[4];
    const float* Wk    = (const float*)d_in[5];
    const float* bk    = (const float*)d_in[6];
    const float* Wv    = (const float*)d_in[7];
    const float* bv    = (const float*)d_in[8];
    const float* Wo    = (const float*)d_in[9];
    const float* bo    = (const float*)d_in[10];
    float* out = (float*)d_out;

    const int final_smem = (128*68 + 64*68 + 64)*4;   // 52480 B
    cudaFuncSetAttribute(final_kernel, cudaFuncAttributeMaxDynamicSharedMemorySize, final_smem);

    gn_stats_part<<<256,256>>>(x);
    gn_stats_final<<<1,32>>>();
    qkv_kernel<<<128,256>>>(x, gamma, beta, Wq, bq, Wk, bk, Wv, bv);
    attn_kernel<<<256,256>>>();
    final_kernel<<<128,256,final_smem>>>(x, gamma, beta, Wo, bo, out);
}